// round 7
// baseline (speedup 1.0000x reference)
#include <cuda_runtime.h>
#include <math.h>

#define N_ 128
#define T_ 1024
#define C_ 256
#define L_ 128
#define NEGH (-(1 << 26))
#define RINGD 32            // emission ring depth (rows)

__device__ float g_loss[N_];
__device__ int   g_ctr;     // cross-CTA completion counter (self-resetting)

// ---------------------------------------------------------------------------
// Single fused kernel: one 1024-thread CTA per sample (grid = 128 = 1/SM).
//  warp 31 (alone on its SMSP): full CTC DP, 8 states/lane in registers +
//    state 256 on lane 31.  Per step: 1 SHFL.UP + 5 LDS (pre-exp'd emissions
//    from the ring) + 9 FADD/FFMA/FMUL.  No EX2, no barriers.
//  24 warps on SMSP0-2: producers.  Each handles rows t == widx (mod 24):
//    LDG row -> exp2f x8 -> STS into ring slot (t&31) -> st.release flag ->
//    logsumexp reduce (accumulates sum_t log Z_t).
//  Flow control: DP publishes consumed-row watermark (volatile smem); a
//    producer may write row r only when r <= watermark + 24.
// ---------------------------------------------------------------------------
__global__ void __launch_bounds__(1024, 1) ctc_all(const float* __restrict__ preds,
                                                   const int*   __restrict__ targets,
                                                   float*       __restrict__ out) {
    const int n    = blockIdx.x;
    const int tid  = threadIdx.x;
    const int wid  = tid >> 5;
    const int lane = tid & 31;

    __shared__ __align__(16) float ring[RINGD * C_];  // 32KB: e^x rows
    __shared__ int   fl[T_];                          // 4KB: per-row ready flags
    __shared__ int   stg[L_];
    __shared__ float wsum[32];
    __shared__ float finm[260];
    __shared__ int   fine_[32];
    __shared__ volatile int s_prog;                   // DP consumed-row watermark

    const float* P = preds + (size_t)n * T_ * C_;
    const float L2E = 1.4426950408889634f;

    if (tid < L_) stg[tid] = targets[n * L_ + tid];
    fl[tid] = 0;
    if (tid < 32) wsum[tid] = 0.0f;
    if (tid == 0) s_prog = -1;
    __syncthreads();

    const unsigned flb = (unsigned)__cvta_generic_to_shared(fl);

    #define WAITFLAG(TIDX)                                                     \
    {   int ff_; unsigned fa_ = flb + 4u * (unsigned)(TIDX);                   \
        do { asm volatile("ld.acquire.cta.shared::cta.b32 %0, [%1];"           \
                          : "=r"(ff_) : "r"(fa_) : "memory");                  \
        } while (!ff_); }

    if (wid == 31) {
        // =================== DP warp ===================
        const int lab0 = stg[4*lane],   lab1 = stg[4*lane+1];
        const int lab2 = stg[4*lane+2], lab3 = stg[4*lane+3];
        const float sk1 = (lane == 0) ? 1.0f : ((lab0 != stg[4*lane-1]) ? 1.0f : 0.0f);
        const float sk3 = (lab1 != lab0) ? 1.0f : 0.0f;
        const float sk5 = (lab2 != lab1) ? 1.0f : 0.0f;
        const float sk7 = (lab3 != lab2) ? 1.0f : 0.0f;
        const float l31 = (lane == 31) ? 1.0f : 0.0f;

        float m0=0,m1=0,m2=0,m3=0,m4=0,m5=0,m6=0,m7=0,m8=0;
        WAITFLAG(0)
        if (lane == 0) { m0 = ring[0]; m1 = ring[lab0]; }   // alpha at t=0
        WAITFLAG(1)
        const float* rb1 = ring + C_;                        // row 1, slot 1
        float eB = rb1[0],    e0 = rb1[lab0], e1 = rb1[lab1];
        float e2 = rb1[lab2], e3 = rb1[lab3];
        float eB8 = eB * l31;
        int   el = 0;
        float fA = (lane == 0) ? 0.0f : 1.0f, fB = 1.0f;

        #define STEP(TV, DO_STAGE)                                             \
        {                                                                      \
            const int t_ = (TV);                                               \
            float nB=0,n0=0,n1=0,n2=0,n3=0;                                    \
            if (DO_STAGE) {                                                    \
                const int ti_ = t_ + 1;                                        \
                WAITFLAG(ti_)                                                  \
                const float* rb_ = ring + ((ti_ & (RINGD-1)) << 8);            \
                nB = rb_[0];    n0 = rb_[lab0]; n1 = rb_[lab1];                \
                n2 = rb_[lab2]; n3 = rb_[lab3];                                \
            }                                                                  \
            float m7n = __shfl_up_sync(0xffffffffu, m7, 1);                    \
            float in1 = (m7n * fA) * fB;                                       \
            m8 = (m8 + m7) * eB8;                                              \
            m7 = fmaf(sk7, m5, m7 + m6) * e3;                                  \
            m6 = (m6 + m5) * eB;                                               \
            m5 = fmaf(sk5, m3, m5 + m4) * e2;                                  \
            m4 = (m4 + m3) * eB;                                               \
            m3 = fmaf(sk3, m1, m3 + m2) * e1;                                  \
            m2 = (m2 + m1) * eB;                                               \
            m1 = fmaf(sk1, in1, m1 + m0) * e0;                                 \
            m0 = (m0 + in1) * eB;                                              \
            if (DO_STAGE) { eB=nB; e0=n0; e1=n1; e2=n2; e3=n3; eB8 = eB*l31; } \
        }

        #define RENORM                                                         \
        {                                                                      \
            float lm = fmaxf(fmaxf(fmaxf(m0,m1),fmaxf(m2,m3)),                 \
                             fmaxf(fmaxf(m4,m5),fmaxf(m6,m7)));                \
            lm = fmaxf(lm, m8);                                                \
            int bts = __float_as_int(lm);                                      \
            int x   = ((bts >> 23) & 255) - 127;                               \
            int elo = (lm > 0.0f) ? (el + x) : NEGH;                           \
            int eln = __shfl_up_sync(0xffffffffu, elo, 1);                     \
            if (lane == 0) eln = NEGH;                                         \
            int elf = max(elo, eln - 40);                                      \
            int elnf = __shfl_up_sync(0xffffffffu, elf, 1);                    \
            if (lane == 0) elnf = NEGH;                                        \
            int jmp = elf - el;                                                \
            int jc  = min(max(127 - jmp, 0), 254);                             \
            float sc = __int_as_float(jc << 23);                               \
            m0*=sc; m1*=sc; m2*=sc; m3*=sc; m4*=sc;                            \
            m5*=sc; m6*=sc; m7*=sc; m8*=sc;                                    \
            el = elf;                                                          \
            int d  = min(elnf - elf, 40);                                      \
            int h1 = d >> 1;                                                   \
            int h2 = d - h1;                                                   \
            fA = __int_as_float(max(h1 + 127, 0) << 23);                       \
            fB = __int_as_float(max(h2 + 127, 0) << 23);                       \
            if (lane == 0) fA = 0.0f;                                          \
        }

        // main: t = 1..1008, 126 chunks of 8 + renorm + watermark publish
        for (int c = 0; c < 126; c++) {
            const int t0 = 1 + 8 * c;
            STEP(t0+0,1) STEP(t0+1,1) STEP(t0+2,1) STEP(t0+3,1)
            STEP(t0+4,1) STEP(t0+5,1) STEP(t0+6,1) STEP(t0+7,1)
            RENORM
            if (lane == 0) s_prog = t0 + 7;
        }
        // tail: t = 1009..1016, renorm, t = 1017..1023
        STEP(1009,1) STEP(1010,1) STEP(1011,1) STEP(1012,1)
        STEP(1013,1) STEP(1014,1) STEP(1015,1) STEP(1016,1)
        RENORM
        if (lane == 0) s_prog = 1016;
        STEP(1017,1) STEP(1018,1) STEP(1019,1) STEP(1020,1)
        STEP(1021,1) STEP(1022,1) STEP(1023,0)
        #undef STEP
        #undef RENORM

        finm[8*lane+0]=m0; finm[8*lane+1]=m1; finm[8*lane+2]=m2; finm[8*lane+3]=m3;
        finm[8*lane+4]=m4; finm[8*lane+5]=m5; finm[8*lane+6]=m6; finm[8*lane+7]=m7;
        if (lane == 31) finm[256] = m8;
        fine_[lane] = el;
    } else if ((wid & 3) != 3) {
        // =================== producer warps (24) ===================
        const int widx = (wid >> 2) * 3 + (wid & 3);   // 0..23
        float acc = 0.0f;
        for (int t = widx; t < T_; t += 24) {
            while (t > s_prog + 24) __nanosleep(128);   // ring back-pressure
            const float4* row = reinterpret_cast<const float4*>(P + (size_t)t * C_);
            float4 a = row[lane];
            float4 b = row[lane + 32];
            float4 ea, eb;
            ea.x = exp2f(a.x*L2E); ea.y = exp2f(a.y*L2E);
            ea.z = exp2f(a.z*L2E); ea.w = exp2f(a.w*L2E);
            eb.x = exp2f(b.x*L2E); eb.y = exp2f(b.y*L2E);
            eb.z = exp2f(b.z*L2E); eb.w = exp2f(b.w*L2E);
            float4* rb = reinterpret_cast<float4*>(ring + ((t & (RINGD-1)) << 8));
            rb[lane]      = ea;
            rb[lane + 32] = eb;
            __syncwarp();                               // all lanes' STS ordered
            if (lane == 0) {
                unsigned fa_ = flb + 4u * (unsigned)t;
                asm volatile("st.release.cta.shared::cta.b32 [%0], %1;"
                             :: "r"(fa_), "r"(1) : "memory");
            }
            float s = ea.x + ea.y + ea.z + ea.w + eb.x + eb.y + eb.z + eb.w;
            #pragma unroll
            for (int o = 16; o; o >>= 1) s += __shfl_xor_sync(0xffffffffu, s, o);
            if (lane == 0) acc += __logf(s);
        }
        if (lane == 0) wsum[wid] = acc;
    }
    __syncthreads();

    if (tid == 0) {
        float slz = 0.0f;
        #pragma unroll
        for (int w = 0; w < 31; w++) slz += wsum[w];
        int tl = 0;
        for (int i = 0; i < L_; i++) tl += (stg[i] != 0);
        const int sa = 2 * tl, sb = 2 * tl - 1;
        float va = finm[sa], vb = finm[sb];
        int ea = fine_[min(sa >> 3, 31)];
        int eb = fine_[min(sb >> 3, 31)];
        int E  = max(ea, eb);
        float fa2 = __int_as_float(max(ea - E + 127, 0) << 23);
        float fb2 = __int_as_float(max(eb - E + 127, 0) << 23);
        float v = va * fa2 + vb * fb2;
        float loss = 0.0f;
        if (v > 0.0f && E > NEGH / 2) {
            float fin = logf(v) + (float)E * 0.69314718055994531f - slz;
            if (fin >= -1e29f) loss = -fin;
        }
        g_loss[n] = loss / (float)(tl > 0 ? tl : 1);

        // last CTA to finish computes the batch mean (graph-replay safe:
        // counter returns to 0 every call)
        __threadfence();
        int old = atomicAdd(&g_ctr, 1);
        if (old == N_ - 1) {
            float ssum = 0.0f;
            #pragma unroll 8
            for (int i = 0; i < N_; i++) ssum += g_loss[i];
            out[0] = ssum / (float)N_;
            g_ctr = 0;
            __threadfence();
        }
    }
    #undef WAITFLAG
}

// ---------------------------------------------------------------------------
extern "C" void kernel_launch(void* const* d_in, const int* in_sizes, int n_in,
                              void* d_out, int out_size) {
    const float* preds   = (const float*)d_in[0];
    const int*   targets = (const int*)d_in[1];

    ctc_all<<<N_, 1024>>>(preds, targets, (float*)d_out);
}

// round 8
// speedup vs baseline: 1.8145x; 1.8145x over previous
#include <cuda_runtime.h>
#include <math.h>

#define N_ 128
#define T_ 1024
#define C_ 256
#define L_ 128
#define NEGH (-(1 << 26))
#define RINGD 32             // ring depth in rows (32 x 1KB = 32KB smem)

__device__ float g_loss[N_];
__device__ int   g_ctr;      // cross-CTA completion counter (self-resetting)

// ---------------------------------------------------------------------------
// One 1024-thread CTA per sample.
//  warp 31 (alone on SMSP3): whole CTC DP in registers, 8 states/lane +
//    state 256 shadowed in every lane (only lane 31's is read).  Emissions
//    self-served: cp.async raw logit rows into a 32-row smem ring, 30-step
//    prefetch lead, 5 LDS + 5 EX2 per step.  Zero cross-warp sync in the loop.
//  24 producer warps on SMSP0-2: stream the same rows and accumulate
//    sum_t log Z_t (logsumexp).  8 warps idle to keep SMSP3 exclusive.
//  Last CTA to finish reduces g_loss -> out[0].
// ---------------------------------------------------------------------------
__global__ void __launch_bounds__(1024, 1) ctc_all(const float* __restrict__ preds,
                                                   const int*   __restrict__ targets,
                                                   float*       __restrict__ out) {
    const int n    = blockIdx.x;
    const int tid  = threadIdx.x;
    const int wid  = tid >> 5;
    const int lane = tid & 31;

    __shared__ __align__(16) float ring[RINGD * C_];
    __shared__ int   stg[L_];
    __shared__ float wsum[32];
    __shared__ float finm[260];
    __shared__ int   fine_[32];

    const float* P = preds + (size_t)n * T_ * C_;
    const float L2E = 1.4426950408889634f;

    if (tid < L_) stg[tid] = targets[n * L_ + tid];
    if (tid < 32) wsum[tid] = 0.0f;
    __syncthreads();

    if (wid == 31) {
        // =================== DP warp ===================
        const int lab0 = stg[4*lane],   lab1 = stg[4*lane+1];
        const int lab2 = stg[4*lane+2], lab3 = stg[4*lane+3];
        const float sk1 = (lane == 0) ? 1.0f : ((lab0 != stg[4*lane-1]) ? 1.0f : 0.0f);
        const float sk3 = (lab1 != lab0) ? 1.0f : 0.0f;
        const float sk5 = (lab2 != lab1) ? 1.0f : 0.0f;
        const float sk7 = (lab3 != lab2) ? 1.0f : 0.0f;

        const unsigned rbase = (unsigned)__cvta_generic_to_shared(ring);
        const char* gw = (const char*)(P + (size_t)1 * C_) + lane * 16;

        // prologue: rows 1..31 -> ring slots 1..31 (one commit group per row)
        #pragma unroll
        for (int r = 1; r <= 31; r++) {
            unsigned dst = rbase + ((unsigned)(r & (RINGD-1)) << 10) + (unsigned)(lane << 4);
            asm volatile("cp.async.cg.shared.global [%0], [%1], 16;" :: "r"(dst), "l"(gw) : "memory");
            asm volatile("cp.async.cg.shared.global [%0], [%1], 16;" :: "r"(dst + 512), "l"(gw + 512) : "memory");
            asm volatile("cp.async.commit_group;" ::: "memory");
            gw += 1024;
        }

        float m0=0,m1=0,m2=0,m3=0,m4=0,m5=0,m6=0,m7=0,m8=0;
        int   el = 0;
        if (lane == 0) {
            m0 = exp2f(__ldg(&P[0])      * L2E);
            m1 = exp2f(__ldg(&P[stg[0]]) * L2E);
        }
        float fA = (lane == 0) ? 0.0f : 1.0f, fB = 1.0f;

        asm volatile("cp.async.wait_group 30;" ::: "memory");   // row 1 resident
        int ci = 256;                       // word offset of row 1 (slot 1)
        float eB = exp2f(ring[ci]        * L2E);
        float e0 = exp2f(ring[ci + lab0] * L2E);
        float e1 = exp2f(ring[ci + lab1] * L2E);
        float e2 = exp2f(ring[ci + lab2] * L2E);
        float e3 = exp2f(ring[ci + lab3] * L2E);
        ci = 512;                           // next staged: row 2
        unsigned woff = 0;                  // byte offset for row 32 (slot 0)

        // STEP with prefetch (valid while t+31 <= 1023): one commit, wait<=30
        #define STEPP                                                          \
        {                                                                      \
            unsigned dst = rbase + woff + (unsigned)(lane << 4);               \
            asm volatile("cp.async.cg.shared.global [%0], [%1], 16;"           \
                         :: "r"(dst), "l"(gw) : "memory");                     \
            asm volatile("cp.async.cg.shared.global [%0], [%1], 16;"           \
                         :: "r"(dst + 512), "l"(gw + 512) : "memory");         \
            asm volatile("cp.async.commit_group;" ::: "memory");               \
            gw += 1024;                                                        \
            woff = (woff + 1024) & (RINGD * 1024 - 1);                         \
            asm volatile("cp.async.wait_group 30;" ::: "memory");              \
            float rB = ring[ci];        float r0 = ring[ci + lab0];            \
            float r1 = ring[ci + lab1]; float r2 = ring[ci + lab2];            \
            float r3 = ring[ci + lab3];                                        \
            float m7n = __shfl_up_sync(0xffffffffu, m7, 1);                    \
            float in1 = (m7n * fA) * fB;                                       \
            m8 = (m8 + m7) * eB;                                               \
            m7 = fmaf(sk7, m5, m7 + m6) * e3;                                  \
            m6 = (m6 + m5) * eB;                                               \
            m5 = fmaf(sk5, m3, m5 + m4) * e2;                                  \
            m4 = (m4 + m3) * eB;                                               \
            m3 = fmaf(sk3, m1, m3 + m2) * e1;                                  \
            m2 = (m2 + m1) * eB;                                               \
            m1 = fmaf(sk1, in1, m1 + m0) * e0;                                 \
            m0 = (m0 + in1) * eB;                                              \
            eB = exp2f(rB * L2E);  e0 = exp2f(r0 * L2E);                       \
            e1 = exp2f(r1 * L2E);  e2 = exp2f(r2 * L2E);                       \
            e3 = exp2f(r3 * L2E);                                              \
            ci = (ci + 256) & (RINGD * 256 - 1);                               \
        }

        // STEP without prefetch/wait (all rows resident); DO_STAGE switchable
        #define STEPT(DO_STAGE)                                                \
        {                                                                      \
            float rB=0,r0=0,r1=0,r2=0,r3=0;                                    \
            if (DO_STAGE) {                                                    \
                rB = ring[ci];        r0 = ring[ci + lab0];                    \
                r1 = ring[ci + lab1]; r2 = ring[ci + lab2];                    \
                r3 = ring[ci + lab3];                                          \
            }                                                                  \
            float m7n = __shfl_up_sync(0xffffffffu, m7, 1);                    \
            float in1 = (m7n * fA) * fB;                                       \
            m8 = (m8 + m7) * eB;                                               \
            m7 = fmaf(sk7, m5, m7 + m6) * e3;                                  \
            m6 = (m6 + m5) * eB;                                               \
            m5 = fmaf(sk5, m3, m5 + m4) * e2;                                  \
            m4 = (m4 + m3) * eB;                                               \
            m3 = fmaf(sk3, m1, m3 + m2) * e1;                                  \
            m2 = (m2 + m1) * eB;                                               \
            m1 = fmaf(sk1, in1, m1 + m0) * e0;                                 \
            m0 = (m0 + in1) * eB;                                              \
            if (DO_STAGE) {                                                    \
                eB = exp2f(rB * L2E);  e0 = exp2f(r0 * L2E);                   \
                e1 = exp2f(r1 * L2E);  e2 = exp2f(r2 * L2E);                   \
                e3 = exp2f(r3 * L2E);                                          \
                ci = (ci + 256) & (RINGD * 256 - 1);                           \
            }                                                                  \
        }

        #define RENORM                                                         \
        {                                                                      \
            float lm = fmaxf(fmaxf(fmaxf(m0,m1),fmaxf(m2,m3)),                 \
                             fmaxf(fmaxf(m4,m5),fmaxf(m6,m7)));                \
            lm = fmaxf(lm, m8);                                                \
            int bts = __float_as_int(lm);                                      \
            int x   = ((bts >> 23) & 255) - 127;                               \
            int elo = (lm > 0.0f) ? (el + x) : NEGH;                           \
            int eln = __shfl_up_sync(0xffffffffu, elo, 1);                     \
            if (lane == 0) eln = NEGH;                                         \
            int elf = max(elo, eln - 40);                                      \
            int elnf = __shfl_up_sync(0xffffffffu, elf, 1);                    \
            if (lane == 0) elnf = NEGH;                                        \
            int jmp = elf - el;                                                \
            int jc  = min(max(127 - jmp, 0), 254);                             \
            float sc = __int_as_float(jc << 23);                               \
            m0*=sc; m1*=sc; m2*=sc; m3*=sc; m4*=sc;                            \
            m5*=sc; m6*=sc; m7*=sc; m8*=sc;                                    \
            el = elf;                                                          \
            int d  = min(elnf - elf, 40);                                      \
            int h1 = d >> 1;                                                   \
            int h2 = d - h1;                                                   \
            fA = __int_as_float(max(h1 + 127, 0) << 23);                       \
            fB = __int_as_float(max(h2 + 127, 0) << 23);                       \
            if (lane == 0) fA = 0.0f;                                          \
        }

        // main: t = 1..992 (124 chunks of 8, prefetching rows 32..1023)
        for (int c = 0; c < 124; c++) {
            STEPP STEPP STEPP STEPP STEPP STEPP STEPP STEPP
            RENORM
        }
        asm volatile("cp.async.wait_group 0;" ::: "memory");    // rows ..1023 in
        // tail: t = 993..1023 (31 steps, no async traffic)
        STEPT(1) STEPT(1) STEPT(1) STEPT(1) STEPT(1) STEPT(1) STEPT(1) STEPT(1)
        RENORM
        STEPT(1) STEPT(1) STEPT(1) STEPT(1) STEPT(1) STEPT(1) STEPT(1) STEPT(1)
        RENORM
        STEPT(1) STEPT(1) STEPT(1) STEPT(1) STEPT(1) STEPT(1) STEPT(1) STEPT(1)
        RENORM
        STEPT(1) STEPT(1) STEPT(1) STEPT(1) STEPT(1) STEPT(1) STEPT(0)
        #undef STEPP
        #undef STEPT
        #undef RENORM

        finm[8*lane+0]=m0; finm[8*lane+1]=m1; finm[8*lane+2]=m2; finm[8*lane+3]=m3;
        finm[8*lane+4]=m4; finm[8*lane+5]=m5; finm[8*lane+6]=m6; finm[8*lane+7]=m7;
        if (lane == 31) finm[256] = m8;
        fine_[lane] = el;
    } else if ((wid & 3) != 3) {
        // =================== producer warps (24): sum_t log Z_t ============
        const int widx = (wid >> 2) * 3 + (wid & 3);   // 0..23
        float acc = 0.0f;
        for (int t = widx; t < T_; t += 24) {
            const float4* row = reinterpret_cast<const float4*>(P + (size_t)t * C_);
            float4 a = row[lane];
            float4 b = row[lane + 32];
            float s = exp2f(a.x*L2E)+exp2f(a.y*L2E)+exp2f(a.z*L2E)+exp2f(a.w*L2E)
                    + exp2f(b.x*L2E)+exp2f(b.y*L2E)+exp2f(b.z*L2E)+exp2f(b.w*L2E);
            #pragma unroll
            for (int o = 16; o; o >>= 1) s += __shfl_xor_sync(0xffffffffu, s, o);
            if (lane == 0) acc += __logf(s);
        }
        if (lane == 0) wsum[wid] = acc;
    }
    __syncthreads();

    if (tid == 0) {
        float slz = 0.0f;
        #pragma unroll
        for (int w = 0; w < 31; w++) slz += wsum[w];
        int tl = 0;
        for (int i = 0; i < L_; i++) tl += (stg[i] != 0);
        const int sa = 2 * tl, sb = 2 * tl - 1;
        float va = finm[sa], vb = finm[sb];
        int ea = fine_[min(sa >> 3, 31)];
        int eb = fine_[min(sb >> 3, 31)];
        int E  = max(ea, eb);
        float fa2 = __int_as_float(max(ea - E + 127, 0) << 23);
        float fb2 = __int_as_float(max(eb - E + 127, 0) << 23);
        float v = va * fa2 + vb * fb2;
        float loss = 0.0f;
        if (v > 0.0f && E > NEGH / 2) {
            float fin = logf(v) + (float)E * 0.69314718055994531f - slz;
            if (fin >= -1e29f) loss = -fin;
        }
        g_loss[n] = loss / (float)(tl > 0 ? tl : 1);

        // last CTA computes the batch mean (self-resetting counter)
        __threadfence();
        int old = atomicAdd(&g_ctr, 1);
        if (old == N_ - 1) {
            float ssum = 0.0f;
            #pragma unroll 8
            for (int i = 0; i < N_; i++) ssum += g_loss[i];
            out[0] = ssum / (float)N_;
            g_ctr = 0;
            __threadfence();
        }
    }
}

// ---------------------------------------------------------------------------
extern "C" void kernel_launch(void* const* d_in, const int* in_sizes, int n_in,
                              void* d_out, int out_size) {
    const float* preds   = (const float*)d_in[0];
    const int*   targets = (const int*)d_in[1];

    ctc_all<<<N_, 1024>>>(preds, targets, (float*)d_out);
}

// round 9
// speedup vs baseline: 2.2264x; 1.2270x over previous
#include <cuda_runtime.h>
#include <math.h>

#define N_ 128
#define T_ 1024
#define C_ 256
#define L_ 128
#define NEGH (-(1 << 26))
#define RINGD 32             // ring depth in rows (32 x 1KB = 32KB smem)

__device__ float g_loss[N_];
__device__ int   g_ctr;      // cross-CTA completion counter (self-resetting)

// ---------------------------------------------------------------------------
// One 1024-thread CTA per sample.  preds read ONCE.
//  24 producer warps (SMSP0-2): LDG row t -> exp2f x8 -> STS exp'd row into
//    ring slot (t&31) -> red.release chunk counter -> logsumexp accumulate.
//  warp 31 (alone on SMSP3): CTC DP, 8 states/lane in registers.  Per step:
//    5 LDS (pre-exp'd emissions) + 1 SHFL + ~24 FLOPs.  Sync amortized:
//    one acquire-poll of a chunk counter per 8 steps; watermark published
//    once per 8 steps for producer back-pressure.
//  Last CTA to finish reduces g_loss -> out[0].
// ---------------------------------------------------------------------------
__global__ void __launch_bounds__(1024, 1) ctc_all(const float* __restrict__ preds,
                                                   const int*   __restrict__ targets,
                                                   float*       __restrict__ out) {
    const int n    = blockIdx.x;
    const int tid  = threadIdx.x;
    const int wid  = tid >> 5;
    const int lane = tid & 31;

    __shared__ __align__(16) float ring[RINGD * C_];  // 32KB exp'd rows
    __shared__ int   cnt[T_ / 8];                     // per-8-row-chunk counters
    __shared__ int   stg[L_];
    __shared__ float wsum[32];
    __shared__ float finm[260];
    __shared__ int   fine_[32];
    __shared__ volatile int s_prog;                   // DP consumed-row watermark

    const float* P = preds + (size_t)n * T_ * C_;
    const float L2E = 1.4426950408889634f;

    if (tid < L_) stg[tid] = targets[n * L_ + tid];
    if (tid < T_ / 8) cnt[tid] = 0;
    if (tid < 32) wsum[tid] = 0.0f;
    if (tid == 0) s_prog = 0;
    __syncthreads();

    const unsigned cntb = (unsigned)__cvta_generic_to_shared(cnt);

    if (wid == 31) {
        // =================== DP warp ===================
        const int lab0 = stg[4*lane],   lab1 = stg[4*lane+1];
        const int lab2 = stg[4*lane+2], lab3 = stg[4*lane+3];
        const float sk1 = (lane == 0) ? 1.0f : ((lab0 != stg[4*lane-1]) ? 1.0f : 0.0f);
        const float sk3 = (lab1 != lab0) ? 1.0f : 0.0f;
        const float sk5 = (lab2 != lab1) ? 1.0f : 0.0f;
        const float sk7 = (lab3 != lab2) ? 1.0f : 0.0f;

        #define WAITCNT(K)                                                     \
        {   int cc_; unsigned ca_ = cntb + 4u * (unsigned)(K);                 \
            do { asm volatile("ld.acquire.cta.shared::cta.b32 %0, [%1];"       \
                              : "=r"(cc_) : "r"(ca_) : "memory");              \
            } while (cc_ < 8); }

        float m0=0,m1=0,m2=0,m3=0,m4=0,m5=0,m6=0,m7=0,m8=0;
        int   el = 0;
        WAITCNT(0)                              // rows 0..7 resident
        if (lane == 0) { m0 = ring[0]; m1 = ring[lab0]; }   // alpha at t=0
        float fA = (lane == 0) ? 0.0f : 1.0f, fB = 1.0f;

        int ci = 256;                           // word offset of row 1 (slot 1)
        float eB = ring[ci];
        float e0 = ring[ci + lab0];
        float e1 = ring[ci + lab1];
        float e2 = ring[ci + lab2];
        float e3 = ring[ci + lab3];
        ci = 512;                               // next staged: row 2

        #define STEPD(DO_STAGE)                                                \
        {                                                                      \
            float nB=0,n0=0,n1=0,n2=0,n3=0;                                    \
            if (DO_STAGE) {                                                    \
                nB = ring[ci];        n0 = ring[ci + lab0];                    \
                n1 = ring[ci + lab1]; n2 = ring[ci + lab2];                    \
                n3 = ring[ci + lab3];                                          \
            }                                                                  \
            float m7n = __shfl_up_sync(0xffffffffu, m7, 1);                    \
            float in1 = (m7n * fA) * fB;                                       \
            m8 = (m8 + m7) * eB;                                               \
            m7 = fmaf(sk7, m5, m7 + m6) * e3;                                  \
            m6 = (m6 + m5) * eB;                                               \
            m5 = fmaf(sk5, m3, m5 + m4) * e2;                                  \
            m4 = (m4 + m3) * eB;                                               \
            m3 = fmaf(sk3, m1, m3 + m2) * e1;                                  \
            m2 = (m2 + m1) * eB;                                               \
            m1 = fmaf(sk1, in1, m1 + m0) * e0;                                 \
            m0 = (m0 + in1) * eB;                                              \
            if (DO_STAGE) {                                                    \
                eB = nB; e0 = n0; e1 = n1; e2 = n2; e3 = n3;                   \
                ci = (ci + 256) & (RINGD * 256 - 1);                           \
            }                                                                  \
        }

        #define RENORM                                                         \
        {                                                                      \
            float lm = fmaxf(fmaxf(fmaxf(m0,m1),fmaxf(m2,m3)),                 \
                             fmaxf(fmaxf(m4,m5),fmaxf(m6,m7)));                \
            lm = fmaxf(lm, m8);                                                \
            int bts = __float_as_int(lm);                                      \
            int x   = ((bts >> 23) & 255) - 127;                               \
            int elo = (lm > 0.0f) ? (el + x) : NEGH;                           \
            int eln = __shfl_up_sync(0xffffffffu, elo, 1);                     \
            if (lane == 0) eln = NEGH;                                         \
            int elf = max(elo, eln - 40);                                      \
            int elnf = __shfl_up_sync(0xffffffffu, elf, 1);                    \
            if (lane == 0) elnf = NEGH;                                        \
            int jmp = elf - el;                                                \
            int jc  = min(max(127 - jmp, 0), 254);                             \
            float sc = __int_as_float(jc << 23);                               \
            m0*=sc; m1*=sc; m2*=sc; m3*=sc; m4*=sc;                            \
            m5*=sc; m6*=sc; m7*=sc; m8*=sc;                                    \
            el = elf;                                                          \
            int d  = min(elnf - elf, 40);                                      \
            int h1 = d >> 1;                                                   \
            int h2 = d - h1;                                                   \
            fA = __int_as_float(max(h1 + 127, 0) << 23);                       \
            fB = __int_as_float(max(h2 + 127, 0) << 23);                       \
            if (lane == 0) fA = 0.0f;                                          \
        }

        // blocks j=0..126: steps 8j+1 .. 8j+8 (stage rows up to 8j+9)
        for (int j = 0; j < 127; j++) {
            WAITCNT(j + 1)                      // rows <= 8j+15 resident
            STEPD(1) STEPD(1) STEPD(1) STEPD(1)
            STEPD(1) STEPD(1) STEPD(1) STEPD(1)
            RENORM
            if (lane == 0) s_prog = 8 * j + 8;  // plain volatile publish
        }
        // tail: steps 1017..1023 (all rows resident after WAITCNT(127))
        STEPD(1) STEPD(1) STEPD(1) STEPD(1) STEPD(1) STEPD(1) STEPD(0)
        #undef STEPD
        #undef RENORM
        #undef WAITCNT

        finm[8*lane+0]=m0; finm[8*lane+1]=m1; finm[8*lane+2]=m2; finm[8*lane+3]=m3;
        finm[8*lane+4]=m4; finm[8*lane+5]=m5; finm[8*lane+6]=m6; finm[8*lane+7]=m7;
        if (lane == 31) finm[256] = m8;
        fine_[lane] = el;
    } else if ((wid & 3) != 3) {
        // =================== producer warps (24) ===================
        const int widx = (wid >> 2) * 3 + (wid & 3);   // 0..23
        float acc = 0.0f;
        for (int t = widx; t < T_; t += 24) {
            while (t - s_prog > 24) __nanosleep(64);   // ring back-pressure
            const float4* row = reinterpret_cast<const float4*>(P + (size_t)t * C_);
            float4 a = row[lane];
            float4 b = row[lane + 32];
            float4 ea, eb;
            ea.x = exp2f(a.x*L2E); ea.y = exp2f(a.y*L2E);
            ea.z = exp2f(a.z*L2E); ea.w = exp2f(a.w*L2E);
            eb.x = exp2f(b.x*L2E); eb.y = exp2f(b.y*L2E);
            eb.z = exp2f(b.z*L2E); eb.w = exp2f(b.w*L2E);
            float4* rb = reinterpret_cast<float4*>(ring + ((t & (RINGD-1)) << 8));
            rb[lane]      = ea;
            rb[lane + 32] = eb;
            __syncwarp();
            if (lane == 0) {
                unsigned ca = (unsigned)__cvta_generic_to_shared(&cnt[t >> 3]);
                asm volatile("red.release.cta.shared::cta.add.u32 [%0], %1;"
                             :: "r"(ca), "r"(1) : "memory");
            }
            float s = ea.x + ea.y + ea.z + ea.w + eb.x + eb.y + eb.z + eb.w;
            #pragma unroll
            for (int o = 16; o; o >>= 1) s += __shfl_xor_sync(0xffffffffu, s, o);
            if (lane == 0) acc += __logf(s);
        }
        if (lane == 0) wsum[wid] = acc;
    }
    __syncthreads();

    if (tid == 0) {
        float slz = 0.0f;
        #pragma unroll
        for (int w = 0; w < 31; w++) slz += wsum[w];
        int tl = 0;
        for (int i = 0; i < L_; i++) tl += (stg[i] != 0);
        const int sa = 2 * tl, sb = 2 * tl - 1;
        float va = finm[sa], vb = finm[sb];
        int ea = fine_[min(sa >> 3, 31)];
        int eb = fine_[min(sb >> 3, 31)];
        int E  = max(ea, eb);
        float fa2 = __int_as_float(max(ea - E + 127, 0) << 23);
        float fb2 = __int_as_float(max(eb - E + 127, 0) << 23);
        float v = va * fa2 + vb * fb2;
        float loss = 0.0f;
        if (v > 0.0f && E > NEGH / 2) {
            float fin = logf(v) + (float)E * 0.69314718055994531f - slz;
            if (fin >= -1e29f) loss = -fin;
        }
        g_loss[n] = loss / (float)(tl > 0 ? tl : 1);

        // last CTA computes the batch mean (self-resetting counter)
        __threadfence();
        int old = atomicAdd(&g_ctr, 1);
        if (old == N_ - 1) {
            float ssum = 0.0f;
            #pragma unroll 8
            for (int i = 0; i < N_; i++) ssum += g_loss[i];
            out[0] = ssum / (float)N_;
            g_ctr = 0;
            __threadfence();
        }
    }
}

// ---------------------------------------------------------------------------
extern "C" void kernel_launch(void* const* d_in, const int* in_sizes, int n_in,
                              void* d_out, int out_size) {
    const float* preds   = (const float*)d_in[0];
    const int*   targets = (const int*)d_in[1];

    ctc_all<<<N_, 1024>>>(preds, targets, (float*)d_out);
}